// round 14
// baseline (speedup 1.0000x reference)
#include <cuda_runtime.h>
#include <math.h>
#include <stdint.h>

// Problem shape (fixed by reference setup_inputs)
#define B_DIM 4
#define S_DIM 2048
#define D_DIM 128
#define NROWS (B_DIM * S_DIM)            // 8192
#define GROUPS_PER_B 64                  // sid in [0,8) x vid in [0,8)
#define NGRP (B_DIM * GROUPS_PER_B)      // 256

#define NBLK1 (NROWS / 8)                // 1024 blocks, 8 rows (warps) each
#define NTHR1 256
#define NBLK2 (NROWS / 256)              // 32 blocks
#define NTHR2 256

// Global group accumulators (R2 layout: three separate arrays). Zeroed at
// module load; K2 re-zeros after consuming -> graph-replay deterministic.
__device__ float        g_C [NGRP];
__device__ float        g_S1[NGRP];
__device__ float        g_S2[NGRP];
__device__ unsigned int g_done2;

__device__ __forceinline__ float warp_sum_f(float v) {
    #pragma unroll
    for (int o = 16; o > 0; o >>= 1)
        v += __shfl_xor_sync(0xFFFFFFFFu, v, o);
    return v;
}

// K1: one row per warp, sync-free, no smem. Mask is a word array (int32 0/1 or
// float32 0.0/1.0 — proven not byte-packed in R1): "word != 0" covers both.
__global__ void __launch_bounds__(NTHR1) psc_stats_kernel(
        const float* __restrict__ target,
        const int*   __restrict__ obs,
        const int*   __restrict__ sid,
        const int*   __restrict__ vid) {
    const int warp = threadIdx.x >> 5;
    const int lane = threadIdx.x & 31;
    const int row  = blockIdx.x * (NTHR1 / 32) + warp;
    const size_t idx4 = (size_t)row * (D_DIM / 4) + lane;

    // Front-batched wide loads (MLP=2 per thread, no barrier anywhere).
    float4 t = reinterpret_cast<const float4*>(target)[idx4];
    int4   m = reinterpret_cast<const int4*>(obs)[idx4];

    int my_s = 0, my_v = 0;
    if (lane == 0) { my_s = sid[row]; my_v = vid[row]; }

    const bool o0 = m.x != 0, o1 = m.y != 0, o2 = m.z != 0, o3 = m.w != 0;

    unsigned int c = (unsigned)o0 + (unsigned)o1 + (unsigned)o2 + (unsigned)o3;
    float s1 = 0.f, s2 = 0.f;
    if (o0) { s1 += t.x; s2 += t.x * t.x; }
    if (o1) { s1 += t.y; s2 += t.y * t.y; }
    if (o2) { s1 += t.z; s2 += t.z * t.z; }
    if (o3) { s1 += t.w; s2 += t.w * t.w; }

    unsigned int cnt = __reduce_add_sync(0xFFFFFFFFu, c);   // HW u32 redux
    s1 = warp_sum_f(s1);
    s2 = warp_sum_f(s2);

    if (lane == 0) {
        int batch = row / S_DIM;
        int g = batch * GROUPS_PER_B + my_s * 8 + my_v;
        atomicAdd(&g_C [g], (float)cnt);   // REDG fire-and-forget
        atomicAdd(&g_S1[g], s1);
        atomicAdd(&g_S2[g], s2);
    }
}

// K2: one row per thread. Read group stats (L1/L2-cached, broadcast-heavy),
// compute loc/scale with safe_div + padding, store. Last block resets the
// accumulators + counter for the next graph replay.
// Output layout: loc [B*S] then scale [B*S].
__global__ void __launch_bounds__(NTHR2) psc_finalize_kernel(
        const int* __restrict__ sid,
        const int* __restrict__ vid,
        float* __restrict__ out) {
    __shared__ int s_last;

    const int tid = threadIdx.x;
    const int row = blockIdx.x * NTHR2 + tid;

    const int s = sid[row];
    const int v = vid[row];
    const int batch = row / S_DIM;
    const int g = batch * GROUPS_PER_B + s * 8 + v;

    float C  = g_C [g];
    float S1 = g_S1[g];
    float S2 = g_S2[g];

    float denC = (C == 0.f) ? 1.f : C;            // safe_div
    float loc  = S1 / denC;

    float num  = S2 - 2.f * loc * S1 + loc * loc * C;   // sum (t-loc)^2*obs
    float denV = C - 1.f;
    if (denV == 0.f) denV = 1.f;                  // safe_div
    float scl  = sqrtf(num / denV + 1e-5f);

    if (s == 0) { loc = 0.f; scl = 1.f; }         // padding rows

    out[row]         = loc;                        // loc  [B*S]
    out[NROWS + row] = scl;                        // scale[B*S]

    // ---- Reset accumulators for next graph replay (last-block election) ----
    __syncthreads();                 // all reads in this block are done
    if (tid == 0) {
        __threadfence();
        unsigned int d = atomicAdd(&g_done2, 1u);
        s_last = (d == NBLK2 - 1);
    }
    __syncthreads();
    if (s_last) {
        if (tid < NGRP) {            // 256 threads, 256 groups
            g_C [tid] = 0.f;
            g_S1[tid] = 0.f;
            g_S2[tid] = 0.f;
        }
        if (tid == 0) g_done2 = 0u;
    }
}

extern "C" void kernel_launch(void* const* d_in, const int* in_sizes, int n_in,
                              void* d_out, int out_size) {
    const float* target = (const float*)d_in[0];
    const int*   obs    = (const int*)d_in[1];
    const int*   sid    = (const int*)d_in[2];
    const int*   vid    = (const int*)d_in[3];
    float*       out    = (float*)d_out;

    (void)in_sizes; (void)n_in; (void)out_size;

    psc_stats_kernel<<<NBLK1, NTHR1>>>(target, obs, sid, vid);
    psc_finalize_kernel<<<NBLK2, NTHR2>>>(sid, vid, out);
}

// round 15
// speedup vs baseline: 1.1463x; 1.1463x over previous
#include <cuda_runtime.h>
#include <math.h>
#include <stdint.h>

// Problem shape (fixed by reference setup_inputs)
#define B_DIM 4
#define S_DIM 2048
#define D_DIM 128
#define NROWS (B_DIM * S_DIM)           // 8192
#define GROUPS_PER_B 64                 // sid in [0,8) x vid in [0,8)

#define NBLK 128                        // single wave, 1 block/SM
#define NTHR 1024                       // 32 warps
#define ROWS_PER_BLK (NROWS / NBLK)     // 64
#define ROWS_PER_WARP 2
#define PART_STRIDE (GROUPS_PER_B * 3)  // 192 floats
#define BLK_PER_BATCH (NBLK / B_DIM)    // 32

// Per-batch accumulators: producers REDG partials in, elected consumer reads
// then resets them. Zero at module load -> graph-replay deterministic.
__device__ float        g_bacc[B_DIM * PART_STRIDE];
__device__ unsigned int g_done[B_DIM];

__device__ __forceinline__ float warp_sum_f(float v) {
    #pragma unroll
    for (int o = 16; o > 0; o >>= 1)
        v += __shfl_xor_sync(0xFFFFFFFFu, v, o);
    return v;
}

// Mask is a word array (int32 0/1 or float32 0.0/1.0 — byte layout disproven
// in R1): "word != 0" is correct for both.
__global__ void __launch_bounds__(NTHR) psc_fused_kernel(
        const float* __restrict__ target,
        const int*   __restrict__ obs,
        const int*   __restrict__ sid,
        const int*   __restrict__ vid,
        float*       __restrict__ out) {
    __shared__ float sgrp[PART_STRIDE];   // block partial / batch sums
    __shared__ float sloc[GROUPS_PER_B];
    __shared__ float sscl[GROUPS_PER_B];
    __shared__ int   s_last;

    const int tid   = threadIdx.x;
    const int warp  = tid >> 5;
    const int lane  = tid & 31;
    const int bid   = blockIdx.x;
    const int batch = bid / BLK_PER_BATCH;

    const int row0  = bid * ROWS_PER_BLK + warp * ROWS_PER_WARP;
    const size_t idx4_0 = (size_t)row0 * (D_DIM / 4) + lane;
    const size_t idx4_1 = idx4_0 + (D_DIM / 4);

    // ---- Front-batched loads: target+mask (MLP=4) ----
    float4 t0 = reinterpret_cast<const float4*>(target)[idx4_0];
    float4 t1 = reinterpret_cast<const float4*>(target)[idx4_1];
    int4   m0 = reinterpret_cast<const int4*>(obs)[idx4_0];
    int4   m1 = reinterpret_cast<const int4*>(obs)[idx4_1];

    // Pre-load emit-phase ids (this block's batch rows tid, tid+1024) so the
    // tail never touches sid/vid. L2-hot, overlapped with the big loads.
    const int erow0 = batch * S_DIM + tid;
    const int erow1 = erow0 + NTHR;
    const int es0 = sid[erow0], ev0 = vid[erow0];
    const int es1 = sid[erow1], ev1 = vid[erow1];

    int my_s = 0, my_v = 0;                 // lanes 0,1 hold row0,row1 group ids
    if (lane < ROWS_PER_WARP) {
        my_s = sid[row0 + lane];
        my_v = vid[row0 + lane];
    }

    if (tid < PART_STRIDE) sgrp[tid] = 0.f;
    __syncthreads();                        // sgrp zeroed before atomics

    const bool a0 = m0.x != 0, a1 = m0.y != 0, a2 = m0.z != 0, a3 = m0.w != 0;
    const bool b0 = m1.x != 0, b1 = m1.y != 0, b2 = m1.z != 0, b3 = m1.w != 0;

    unsigned int c0 = (unsigned)a0 + (unsigned)a1 + (unsigned)a2 + (unsigned)a3;
    unsigned int c1 = (unsigned)b0 + (unsigned)b1 + (unsigned)b2 + (unsigned)b3;
    float s10 = 0.f, s20 = 0.f, s11 = 0.f, s21 = 0.f;
    if (a0) { s10 += t0.x; s20 += t0.x * t0.x; }
    if (a1) { s10 += t0.y; s20 += t0.y * t0.y; }
    if (a2) { s10 += t0.z; s20 += t0.z * t0.z; }
    if (a3) { s10 += t0.w; s20 += t0.w * t0.w; }
    if (b0) { s11 += t1.x; s21 += t1.x * t1.x; }
    if (b1) { s11 += t1.y; s21 += t1.y * t1.y; }
    if (b2) { s11 += t1.z; s21 += t1.z * t1.z; }
    if (b3) { s11 += t1.w; s21 += t1.w * t1.w; }

    unsigned int cA = __reduce_add_sync(0xFFFFFFFFu, c0);
    unsigned int cB = __reduce_add_sync(0xFFFFFFFFu, c1);
    s10 = warp_sum_f(s10);
    s11 = warp_sum_f(s11);
    s20 = warp_sum_f(s20);
    s21 = warp_sum_f(s21);

    // Lane 0 commits row0, lane 1 commits row1 (spread-address ATOMS).
    if (lane < ROWS_PER_WARP) {
        float cc = (lane == 0) ? (float)cA : (float)cB;
        float x1 = (lane == 0) ? s10 : s11;
        float x2 = (lane == 0) ? s20 : s21;
        int g = (my_s * 8 + my_v) * 3;
        atomicAdd(&sgrp[g + 0], cc);
        atomicAdd(&sgrp[g + 1], x1);
        atomicAdd(&sgrp[g + 2], x2);
    }
    __syncthreads();

    // ---- Commit block partial straight into per-batch accumulator (REDG) ----
    float* bacc = g_bacc + batch * PART_STRIDE;
    if (tid < PART_STRIDE)
        atomicAdd(bacc + tid, sgrp[tid]);   // 192 REDs, 8-way time-spread

    // ---- Last-block-per-batch election ----
    __syncthreads();           // all RED/ATOMS issued
    if (tid == 0) {
        __threadfence();
        unsigned int d = atomicAdd(&g_done[batch], 1u);
        s_last = (d == BLK_PER_BATCH - 1);
    }
    __syncthreads();
    if (!s_last) return;       // all but 4 blocks exit

    // ---- Tail (last block per batch): one parallel read wave, then emit ----
    if (tid < PART_STRIDE) {
        sgrp[tid] = __ldcg(bacc + tid);     // single L2 round-trip, 192 lanes
        bacc[tid] = 0.f;                    // consumer reset for next replay
    }
    if (tid == NTHR - 1) g_done[batch] = 0u;
    __syncthreads();

    if (tid < GROUPS_PER_B) {
        float C  = sgrp[tid * 3 + 0];
        float S1 = sgrp[tid * 3 + 1];
        float S2 = sgrp[tid * 3 + 2];

        float denC = (C == 0.f) ? 1.f : C;          // safe_div
        float loc  = S1 / denC;

        float num  = S2 - 2.f * loc * S1 + loc * loc * C;  // sum (t-loc)^2*obs
        float denV = C - 1.f;
        if (denV == 0.f) denV = 1.f;                // safe_div
        sloc[tid] = loc;
        sscl[tid] = sqrtf(num / denV + 1e-5f);
    }
    __syncthreads();

    // Emit with pre-loaded ids: zero loads on this path.
    {
        int g0 = es0 * 8 + ev0;
        float l0 = sloc[g0], c0v = sscl[g0];
        if (es0 == 0) { l0 = 0.f; c0v = 1.f; }      // padding rows
        out[erow0]         = l0;
        out[NROWS + erow0] = c0v;

        int g1 = es1 * 8 + ev1;
        float l1 = sloc[g1], c1v = sscl[g1];
        if (es1 == 0) { l1 = 0.f; c1v = 1.f; }
        out[erow1]         = l1;
        out[NROWS + erow1] = c1v;
    }
}

extern "C" void kernel_launch(void* const* d_in, const int* in_sizes, int n_in,
                              void* d_out, int out_size) {
    const float* target = (const float*)d_in[0];
    const int*   obs    = (const int*)d_in[1];
    const int*   sid    = (const int*)d_in[2];
    const int*   vid    = (const int*)d_in[3];
    float*       out    = (float*)d_out;

    (void)in_sizes; (void)n_in; (void)out_size;

    psc_fused_kernel<<<NBLK, NTHR>>>(target, obs, sid, vid, out);
}

// round 16
// speedup vs baseline: 1.1783x; 1.0280x over previous
#include <cuda_runtime.h>
#include <math.h>
#include <stdint.h>

// Problem shape (fixed by reference setup_inputs)
#define B_DIM 4
#define S_DIM 2048
#define D_DIM 128
#define NROWS (B_DIM * S_DIM)           // 8192
#define GROUPS_PER_B 64                 // sid in [0,8) x vid in [0,8)

#define NBLK 128                        // single wave, 1 block/SM
#define NTHR 1024                       // 32 warps
#define ROWS_PER_BLK (NROWS / NBLK)     // 64
#define ROWS_PER_WARP 2
#define PART_STRIDE (GROUPS_PER_B * 3)  // 192 floats
#define BLK_PER_BATCH (NBLK / B_DIM)    // 32

// Per-batch accumulators: producers REDG partials in, elected consumer reads
// then resets them. Zero at module load -> graph-replay deterministic.
__device__ float        g_bacc[B_DIM * PART_STRIDE];
__device__ unsigned int g_done[B_DIM];

__device__ __forceinline__ float warp_sum_f(float v) {
    #pragma unroll
    for (int o = 16; o > 0; o >>= 1)
        v += __shfl_xor_sync(0xFFFFFFFFu, v, o);
    return v;
}

// Mask is a word array (int32 0/1 or float32 0.0/1.0 — byte layout disproven
// in R1): "word != 0" is correct for both.
__global__ void __launch_bounds__(NTHR) psc_fused_kernel(
        const float* __restrict__ target,
        const int*   __restrict__ obs,
        const int*   __restrict__ sid,
        const int*   __restrict__ vid,
        float*       __restrict__ out) {
    __shared__ float sgrp[PART_STRIDE];   // block partial / batch sums
    __shared__ float sloc[GROUPS_PER_B];
    __shared__ float sscl[GROUPS_PER_B];
    __shared__ int   s_last;

    const int tid   = threadIdx.x;
    const int warp  = tid >> 5;
    const int lane  = tid & 31;
    const int bid   = blockIdx.x;
    const int batch = bid / BLK_PER_BATCH;

    const int row0  = bid * ROWS_PER_BLK + warp * ROWS_PER_WARP;
    const size_t idx4_0 = (size_t)row0 * (D_DIM / 4) + lane;
    const size_t idx4_1 = idx4_0 + (D_DIM / 4);

    // ---- Front-batched wide loads: MLP=4, one DRAM round-trip ----
    float4 t0 = reinterpret_cast<const float4*>(target)[idx4_0];
    float4 t1 = reinterpret_cast<const float4*>(target)[idx4_1];
    int4   m0 = reinterpret_cast<const int4*>(obs)[idx4_0];
    int4   m1 = reinterpret_cast<const int4*>(obs)[idx4_1];

    int my_s = 0, my_v = 0;                 // lanes 0,1 hold row0,row1 group ids
    if (lane < ROWS_PER_WARP) {
        my_s = sid[row0 + lane];
        my_v = vid[row0 + lane];
    }

    if (tid < PART_STRIDE) sgrp[tid] = 0.f;
    __syncthreads();                        // sgrp zeroed before atomics

    const bool a0 = m0.x != 0, a1 = m0.y != 0, a2 = m0.z != 0, a3 = m0.w != 0;
    const bool b0 = m1.x != 0, b1 = m1.y != 0, b2 = m1.z != 0, b3 = m1.w != 0;

    unsigned int c0 = (unsigned)a0 + (unsigned)a1 + (unsigned)a2 + (unsigned)a3;
    unsigned int c1 = (unsigned)b0 + (unsigned)b1 + (unsigned)b2 + (unsigned)b3;
    float s10 = 0.f, s20 = 0.f, s11 = 0.f, s21 = 0.f;
    if (a0) { s10 += t0.x; s20 += t0.x * t0.x; }
    if (a1) { s10 += t0.y; s20 += t0.y * t0.y; }
    if (a2) { s10 += t0.z; s20 += t0.z * t0.z; }
    if (a3) { s10 += t0.w; s20 += t0.w * t0.w; }
    if (b0) { s11 += t1.x; s21 += t1.x * t1.x; }
    if (b1) { s11 += t1.y; s21 += t1.y * t1.y; }
    if (b2) { s11 += t1.z; s21 += t1.z * t1.z; }
    if (b3) { s11 += t1.w; s21 += t1.w * t1.w; }

    unsigned int cA = __reduce_add_sync(0xFFFFFFFFu, c0);
    unsigned int cB = __reduce_add_sync(0xFFFFFFFFu, c1);
    s10 = warp_sum_f(s10);
    s11 = warp_sum_f(s11);
    s20 = warp_sum_f(s20);
    s21 = warp_sum_f(s21);

    // Lane 0 commits row0, lane 1 commits row1 (spread-address ATOMS).
    if (lane < ROWS_PER_WARP) {
        float cc = (lane == 0) ? (float)cA : (float)cB;
        float x1 = (lane == 0) ? s10 : s11;
        float x2 = (lane == 0) ? s20 : s21;
        int g = (my_s * 8 + my_v) * 3;
        atomicAdd(&sgrp[g + 0], cc);
        atomicAdd(&sgrp[g + 1], x1);
        atomicAdd(&sgrp[g + 2], x2);
    }
    __syncthreads();

    // ---- Commit block partial into per-batch accumulator (192 REDG) ----
    float* bacc = g_bacc + batch * PART_STRIDE;
    if (tid < PART_STRIDE)
        atomicAdd(bacc + tid, sgrp[tid]);

    // ---- Last-block-per-batch election ----
    __syncthreads();           // all RED/ATOMS issued
    if (tid == 0) {
        __threadfence();
        unsigned int d = atomicAdd(&g_done[batch], 1u);
        s_last = (d == BLK_PER_BATCH - 1);
    }
    __syncthreads();
    if (!s_last) return;       // all but 4 blocks exit

    // ---- Tail (4 elected blocks): one parallel read wave, then emit ----
    if (tid < PART_STRIDE) {
        sgrp[tid] = __ldcg(bacc + tid);     // single L2 round-trip
        bacc[tid] = 0.f;                    // consumer reset for next replay
    }
    if (tid == NTHR - 1) g_done[batch] = 0u;
    __syncthreads();

    if (tid < GROUPS_PER_B) {
        float C  = sgrp[tid * 3 + 0];
        float S1 = sgrp[tid * 3 + 1];
        float S2 = sgrp[tid * 3 + 2];

        float denC = (C == 0.f) ? 1.f : C;          // safe_div
        float loc  = S1 / denC;

        float num  = S2 - 2.f * loc * S1 + loc * loc * C;  // sum (t-loc)^2*obs
        float denV = C - 1.f;
        if (denV == 0.f) denV = 1.f;                // safe_div
        sloc[tid] = loc;
        sscl[tid] = sqrtf(num / denV + 1e-5f);
    }
    __syncthreads();

    // Vectorized emit: thread t owns adjacent rows 2t, 2t+1 of this batch.
    // S_DIM/2 == NTHR -> exactly one iteration; int2 id loads, float2 stores.
    {
        const int pair = tid;                        // 0..1023
        const int rbase = batch * S_DIM + 2 * pair;  // even row
        int2 s2 = reinterpret_cast<const int2*>(sid)[batch * NTHR + pair];
        int2 v2 = reinterpret_cast<const int2*>(vid)[batch * NTHR + pair];

        int g0 = s2.x * 8 + v2.x;
        int g1 = s2.y * 8 + v2.y;
        float2 lv, cv;
        lv.x = sloc[g0]; cv.x = sscl[g0];
        lv.y = sloc[g1]; cv.y = sscl[g1];
        if (s2.x == 0) { lv.x = 0.f; cv.x = 1.f; }   // padding rows
        if (s2.y == 0) { lv.y = 0.f; cv.y = 1.f; }

        reinterpret_cast<float2*>(out)[rbase / 2]           = lv;  // loc
        reinterpret_cast<float2*>(out)[(NROWS + rbase) / 2] = cv;  // scale
    }
}

extern "C" void kernel_launch(void* const* d_in, const int* in_sizes, int n_in,
                              void* d_out, int out_size) {
    const float* target = (const float*)d_in[0];
    const int*   obs    = (const int*)d_in[1];
    const int*   sid    = (const int*)d_in[2];
    const int*   vid    = (const int*)d_in[3];
    float*       out    = (float*)d_out;

    (void)in_sizes; (void)n_in; (void)out_size;

    psc_fused_kernel<<<NBLK, NTHR>>>(target, obs, sid, vid, out);
}